// round 6
// baseline (speedup 1.0000x reference)
#include <cuda_runtime.h>
#include <math.h>

#define H_IN 321
#define W_IN 321
#define WS 41
#define NPIX 1681
#define NCH 21
#define CP 24
#define NBATCH 16
#define NITERS 10

#define INVSC (321.0f/41.0f)
#define AG 8.0f                 /* 1/(2*(3/12)^2) */
#define SA 0.10606601718f       /* sqrt(ABF), ABF=0.01125 */
#define SB 0.05439282932f       /* sqrt(1/338) */
#define CG 3.0f
#define CB 10.0f
#define EPSV 1e-5f

#define KSTRIDE_H 1688          /* padded bf16 K row stride (x2B = 3376, 16B aligned) */
#define KSPLIT 6
#define KSEG 281                /* 6*281 = 1686 >= 1681 */
#define TILE_M 128
#define KCH2 32
#define NLB 64

__device__ __forceinline__ int div41(int j) { return (j*51151) >> 21; }

// ---------------- static device buffers ----------------
static __device__ float  g_feat[NBATCH*NPIX*8];   // ax,ay,br,bg,bb,nrm,x,y
static __device__ float  g_rsg[NPIX];
static __device__ float  g_rsb[NBATCH*NPIX];
static __device__ float  g_probs[NBATCH*NPIX*CP];
static __device__ float  g_logu[NBATCH*NPIX*CP];
static __device__ float  g_Qa[NBATCH*NPIX*CP];
static __device__ float  g_Qb[NBATCH*NPIX*CP];
static __device__ float  g_part[(size_t)KSPLIT*NBATCH*NPIX*CP];
static __device__ float  g_lpart[NLB];
static __device__ unsigned short g_Kh[(size_t)NBATCH*NPIX*KSTRIDE_H + 4096]; // bf16 Keff

// ---------------- setup ----------------

__global__ void k_rsg() {
    int i = blockIdx.x*blockDim.x + threadIdx.x;
    if (i >= NPIX) return;
    int y = div41(i), x = i - y*41;
    float Sx = 0.f, Sy = 0.f;
    for (int j = 0; j < WS; j++) {
        int dx = x - j; Sx += expf(-AG * (float)(dx*dx));
        int dy = y - j; Sy += expf(-AG * (float)(dy*dy));
    }
    g_rsg[i] = rsqrtf(Sx*Sy - 1.0f);
}

// resize (jax linear/antialias, scale 321/41) -> feature vectors
__global__ void k_resize(const float* __restrict__ img) {
    int t = blockIdx.x*blockDim.x + threadIdx.x;
    if (t >= NBATCH*NPIX) return;
    int n = t / NPIX, p = t - n*NPIX;
    int oy = div41(p), ox = p - oy*41;

    float wy[18], wx[18];
    float sy = (oy + 0.5f)*INVSC - 0.5f;
    int jy0 = max(0, (int)ceilf(sy - INVSC));
    int jy1 = min(H_IN-1, (int)floorf(sy + INVSC));
    float sumy = 0.f;
    for (int j = jy0; j <= jy1; j++) {
        float w = fmaxf(1.0f - fabsf(sy - (float)j)*(1.0f/INVSC), 0.f);
        wy[j-jy0] = w; sumy += w;
    }
    float sx = (ox + 0.5f)*INVSC - 0.5f;
    int jx0 = max(0, (int)ceilf(sx - INVSC));
    int jx1 = min(W_IN-1, (int)floorf(sx + INVSC));
    float sumx = 0.f;
    for (int j = jx0; j <= jx1; j++) {
        float w = fmaxf(1.0f - fabsf(sx - (float)j)*(1.0f/INVSC), 0.f);
        wx[j-jx0] = w; sumx += w;
    }

    float a0 = 0.f, a1 = 0.f, a2 = 0.f;
    const float* b0 = img + (size_t)(n*3 + 0)*H_IN*W_IN;
    const float* b1 = img + (size_t)(n*3 + 1)*H_IN*W_IN;
    const float* b2 = img + (size_t)(n*3 + 2)*H_IN*W_IN;
    for (int jy = jy0; jy <= jy1; jy++) {
        float wyv = wy[jy-jy0];
        const float* r0 = b0 + (size_t)jy*W_IN;
        const float* r1 = b1 + (size_t)jy*W_IN;
        const float* r2 = b2 + (size_t)jy*W_IN;
        for (int jx = jx0; jx <= jx1; jx++) {
            float w = wyv * wx[jx-jx0];
            a0 = fmaf(w, r0[jx], a0);
            a1 = fmaf(w, r1[jx], a1);
            a2 = fmaf(w, r2[jx], a2);
        }
    }
    float inv = 1.0f/(sumy*sumx);
    float fx = (float)ox, fy = (float)oy;
    float ax = fx*SA, ay = fy*SA;
    float br = a0*inv*SB, bg = a1*inv*SB, bb = a2*inv*SB;
    float nrm = ax*ax + ay*ay + br*br + bg*bg + bb*bb;
    float4* F = (float4*)(g_feat + (size_t)t*8);
    F[0] = make_float4(ax, ay, br, bg);
    F[1] = make_float4(bb, nrm, fx, fy);
}

__global__ void k_probs(const float* __restrict__ pred) {
    int t = blockIdx.x*blockDim.x + threadIdx.x;
    if (t >= NBATCH*NPIX) return;
    int n = t / NPIX, p = t - n*NPIX;
    const float* base = pred + (size_t)n*NCH*NPIX + p;
    float x[NCH];
    float m = -1e30f;
    #pragma unroll
    for (int c = 0; c < NCH; c++) { x[c] = base[(size_t)c*NPIX]; m = fmaxf(m, x[c]); }
    float s = 0.f;
    #pragma unroll
    for (int c = 0; c < NCH; c++) { x[c] = __expf(x[c]-m); s += x[c]; }
    float inv = 1.0f/s;
    float s2 = 0.f;
    #pragma unroll
    for (int c = 0; c < NCH; c++) { x[c] = fminf(fmaxf(x[c]*inv, EPSV), 1.0f); s2 += x[c]; }
    float inv2 = 1.0f/s2;
    float* pp = g_probs + (size_t)t*CP;
    float* pl = g_logu  + (size_t)t*CP;
    float* pq = g_Qa    + (size_t)t*CP;
    #pragma unroll
    for (int c = 0; c < NCH; c++) {
        float v = x[c]*inv2;
        pp[c] = v; pl[c] = __logf(v); pq[c] = v;
    }
    #pragma unroll
    for (int c = NCH; c < CP; c++) { pp[c] = 0.f; pl[c] = 0.f; pq[c] = 0.f; }
}

// bilateral row sums via gram form (self term = 1, subtracted at end)
__global__ void k_sums() {
    int i = blockIdx.x, n = blockIdx.y;
    int tid = threadIdx.x;
    const float4* F = (const float4*)(g_feat + (size_t)(n*NPIX)*8);
    float4 fa = F[2*i], fb = F[2*i+1];
    float f0 = 2.f*fa.x, f1 = 2.f*fa.y, f2 = 2.f*fa.z, f3 = 2.f*fa.w, f4 = 2.f*fb.x;
    float ni = fb.y;
    float sum = 0.f;
    for (int j = tid; j < NPIX; j += 256) {
        float4 ja = F[2*j], jb = F[2*j+1];
        float e = -ni - jb.y;
        e = fmaf(f0, ja.x, e); e = fmaf(f1, ja.y, e); e = fmaf(f2, ja.z, e);
        e = fmaf(f3, ja.w, e); e = fmaf(f4, jb.x, e);
        sum += __expf(e);
    }
    for (int o = 16; o; o >>= 1) sum += __shfl_down_sync(0xffffffffu, sum, o);
    __shared__ float red[8];
    int wid = tid >> 5, lane = tid & 31;
    if (lane == 0) red[wid] = sum;
    __syncthreads();
    if (wid == 0) {
        float v = (lane < 8) ? red[lane] : 0.f;
        for (int o = 4; o; o >>= 1) v += __shfl_down_sync(0xffffffffu, v, o);
        if (lane == 0) g_rsb[n*NPIX + i] = rsqrtf(v - 1.0f);
    }
}

__device__ __forceinline__ float keff_val(
    float f0, float f1, float f2, float f3, float f4, float ni,
    float xi, float yi, float rsbi, float rsgi,
    const float4* F, const float* rsb, int j, int i)
{
    float4 ja = F[2*j], jb = F[2*j+1];
    float e = -ni - jb.y;
    e = fmaf(f0, ja.x, e); e = fmaf(f1, ja.y, e); e = fmaf(f2, ja.z, e);
    e = fmaf(f3, ja.w, e); e = fmaf(f4, jb.x, e);
    float kb = __expf(e) * rsbi * rsb[j];
    float dx = xi - jb.z, dy = yi - jb.w;
    float d2 = fmaf(dx, dx, dy*dy);
    float v = CB * kb;
    if (d2 < 12.5f) v = fmaf(CG, __expf(-AG*d2)*rsgi*g_rsg[j], v);
    if (j == i) v = 0.f;
    return v;
}

// fused Keff = 10*Kb_norm + 3*Kg_norm, diag 0, bf16 pairs
__global__ void k_keff() {
    int jp = blockIdx.x*blockDim.x + threadIdx.x;   // pair index
    if (jp >= KSTRIDE_H/2) return;
    int i = blockIdx.y, n = blockIdx.z;
    const float4* F = (const float4*)(g_feat + (size_t)(n*NPIX)*8);
    const float* rsb = g_rsb + n*NPIX;
    float4 fa = F[2*i], fb = F[2*i+1];
    float f0 = 2.f*fa.x, f1 = 2.f*fa.y, f2 = 2.f*fa.z, f3 = 2.f*fa.w, f4 = 2.f*fb.x;
    float ni = fb.y, xi = fb.z, yi = fb.w;
    float rsbi = rsb[i], rsgi = g_rsg[i];
    int j0 = 2*jp, j1 = 2*jp + 1;
    float v0 = (j0 < NPIX) ? keff_val(f0,f1,f2,f3,f4,ni,xi,yi,rsbi,rsgi,F,rsb,j0,i) : 0.f;
    float v1 = (j1 < NPIX) ? keff_val(f0,f1,f2,f3,f4,ni,xi,yi,rsbi,rsgi,F,rsb,j1,i) : 0.f;
    unsigned int pk;
    asm("cvt.rn.bf16x2.f32 %0, %1, %2;" : "=r"(pk) : "f"(v1), "f"(v0)); // lo=v0, hi=v1
    *(unsigned int*)(g_Kh + (size_t)(n*NPIX + i)*KSTRIDE_H + 2*jp) = pk;
}

// ---------------- mean-field msg GEMM ----------------
// part[kz][n][row][c] = sum_{k in seg} K[k][row] * Q[k][c]   (K symmetric, bf16)
// thread tile: 4 rows (2 f32x2 pairs) x 6 channels. Q pre-duplicated in smem.
__global__ void __launch_bounds__(128) k_msg(int dir) {
    __shared__ float Kt[KCH2][TILE_M];     // 16 KB fp32 (converted from bf16)
    __shared__ float Qt2[KCH2][48];        // 6 KB duplicated Q pairs
    const float* Qin = dir ? g_Qb : g_Qa;
    int n = blockIdx.z, kz = blockIdx.y;
    int rowbase = blockIdx.x * TILE_M;
    int tid = threadIdx.x;
    int ng = tid & 3, mg = tid >> 2;       // ng: 6-ch group, mg: 4-row group
    int kbase = kz*KSEG, kend = min(NPIX, kbase + KSEG);
    const float* __restrict__ Qn = Qin + (size_t)n*NPIX*CP;
    const unsigned short* __restrict__ Kn = g_Kh + (size_t)n*NPIX*KSTRIDE_H;

    unsigned long long a[12];
    #pragma unroll
    for (int u = 0; u < 12; u++) a[u] = 0ull;

    for (int k0 = kbase; k0 < kend; k0 += KCH2) {
        int kc = min(KCH2, kend - k0);
        // stage K tile: bf16 -> fp32 via shift
        for (int idx = tid; idx < kc*(TILE_M/8); idx += 128) {
            int kk = idx >> 4, g8 = idx & 15;
            uint4 raw = *(const uint4*)(Kn + (size_t)(k0+kk)*KSTRIDE_H + rowbase + g8*8);
            float4 A, B;
            A.x = __uint_as_float(raw.x << 16); A.y = __uint_as_float(raw.x & 0xffff0000u);
            A.z = __uint_as_float(raw.y << 16); A.w = __uint_as_float(raw.y & 0xffff0000u);
            B.x = __uint_as_float(raw.z << 16); B.y = __uint_as_float(raw.z & 0xffff0000u);
            B.z = __uint_as_float(raw.w << 16); B.w = __uint_as_float(raw.w & 0xffff0000u);
            *(float4*)&Kt[kk][g8*8]     = A;
            *(float4*)&Kt[kk][g8*8 + 4] = B;
        }
        // stage Q duplicated: {q,q} pairs
        for (int idx = tid; idx < kc*6; idx += 128) {
            int kk = idx / 6, f4 = idx - kk*6;
            float4 v = *((const float4*)(Qn + (size_t)(k0+kk)*CP) + f4);
            *(float4*)&Qt2[kk][8*f4]     = make_float4(v.x, v.x, v.y, v.y);
            *(float4*)&Qt2[kk][8*f4 + 4] = make_float4(v.z, v.z, v.w, v.w);
        }
        __syncthreads();
        #pragma unroll 4
        for (int kk = 0; kk < kc; kk++) {
            ulonglong2 kp = *(const ulonglong2*)&Kt[kk][mg*4];
            const ulonglong2* qp = (const ulonglong2*)&Qt2[kk][ng*12];
            ulonglong2 qA = qp[0], qB = qp[1], qC = qp[2];
            asm("fma.rn.f32x2 %0, %1, %2, %0;" : "+l"(a[0])  : "l"(kp.x), "l"(qA.x));
            asm("fma.rn.f32x2 %0, %1, %2, %0;" : "+l"(a[1])  : "l"(kp.x), "l"(qA.y));
            asm("fma.rn.f32x2 %0, %1, %2, %0;" : "+l"(a[2])  : "l"(kp.x), "l"(qB.x));
            asm("fma.rn.f32x2 %0, %1, %2, %0;" : "+l"(a[3])  : "l"(kp.x), "l"(qB.y));
            asm("fma.rn.f32x2 %0, %1, %2, %0;" : "+l"(a[4])  : "l"(kp.x), "l"(qC.x));
            asm("fma.rn.f32x2 %0, %1, %2, %0;" : "+l"(a[5])  : "l"(kp.x), "l"(qC.y));
            asm("fma.rn.f32x2 %0, %1, %2, %0;" : "+l"(a[6])  : "l"(kp.y), "l"(qA.x));
            asm("fma.rn.f32x2 %0, %1, %2, %0;" : "+l"(a[7])  : "l"(kp.y), "l"(qA.y));
            asm("fma.rn.f32x2 %0, %1, %2, %0;" : "+l"(a[8])  : "l"(kp.y), "l"(qB.x));
            asm("fma.rn.f32x2 %0, %1, %2, %0;" : "+l"(a[9])  : "l"(kp.y), "l"(qB.y));
            asm("fma.rn.f32x2 %0, %1, %2, %0;" : "+l"(a[10]) : "l"(kp.y), "l"(qC.x));
            asm("fma.rn.f32x2 %0, %1, %2, %0;" : "+l"(a[11]) : "l"(kp.y), "l"(qC.y));
        }
        __syncthreads();
    }

    // a[rp*6 + c] = {row mg*4+2rp (lo), row mg*4+2rp+1 (hi)}
    float* pb = g_part + (((size_t)kz*NBATCH + n)*NPIX)*CP;
    #pragma unroll
    for (int rp = 0; rp < 2; rp++) {
        float lo[6], hi[6];
        #pragma unroll
        for (int c = 0; c < 6; c++)
            asm("mov.b64 {%0,%1}, %2;" : "=f"(lo[c]), "=f"(hi[c]) : "l"(a[rp*6+c]));
        int r0 = rowbase + mg*4 + 2*rp;
        if (r0 < NPIX) {
            float* o = pb + (size_t)r0*CP + ng*6;
            *(float2*)(o)   = make_float2(lo[0], lo[1]);
            *(float2*)(o+2) = make_float2(lo[2], lo[3]);
            *(float2*)(o+4) = make_float2(lo[4], lo[5]);
        }
        if (r0 + 1 < NPIX) {
            float* o = pb + (size_t)(r0+1)*CP + ng*6;
            *(float2*)(o)   = make_float2(hi[0], hi[1]);
            *(float2*)(o+2) = make_float2(hi[2], hi[3]);
            *(float2*)(o+4) = make_float2(hi[4], hi[5]);
        }
    }
}

// combine partials + softmax with logu
__global__ void k_update(int dir) {
    int t = blockIdx.x*blockDim.x + threadIdx.x;
    if (t >= NBATCH*NPIX) return;
    float* Qout = dir ? g_Qa : g_Qb;
    const float* lg = g_logu + (size_t)t*CP;
    float lt[NCH];
    float m = -1e30f;
    #pragma unroll
    for (int c = 0; c < NCH; c++) {
        float s = lg[c];
        #pragma unroll
        for (int kz = 0; kz < KSPLIT; kz++)
            s += g_part[(size_t)kz*NBATCH*NPIX*CP + (size_t)t*CP + c];
        lt[c] = s;
        m = fmaxf(m, s);
    }
    float s = 0.f;
    #pragma unroll
    for (int c = 0; c < NCH; c++) { lt[c] = __expf(lt[c]-m); s += lt[c]; }
    float inv = 1.0f/s;
    float* o = Qout + (size_t)t*CP;
    #pragma unroll
    for (int c = 0; c < NCH; c++) o[c] = lt[c]*inv;
    o[21] = 0.f; o[22] = 0.f; o[23] = 0.f;
}

// ---------------- loss ----------------
__global__ void k_loss1() {
    int tid = threadIdx.x;
    float part = 0.f;
    for (int t = blockIdx.x*256 + tid; t < NBATCH*NPIX; t += NLB*256) {
        const float* q  = g_Qa    + (size_t)t*CP;
        const float* pr = g_probs + (size_t)t*CP;
        float ps[NCH];
        float s = 0.f;
        #pragma unroll
        for (int c = 0; c < NCH; c++) { ps[c] = fmaxf(q[c], EPSV); s += ps[c]; }
        float inv = 1.0f/s;
        #pragma unroll
        for (int c = 0; c < NCH; c++) {
            float p = ps[c]*inv;
            float r = p/pr[c];
            r = fminf(fmaxf(r, 0.05f), 20.0f);
            part += p*__logf(r);
        }
    }
    for (int o = 16; o; o >>= 1) part += __shfl_down_sync(0xffffffffu, part, o);
    __shared__ float red[8];
    int wid = tid >> 5, lane = tid & 31;
    if (lane == 0) red[wid] = part;
    __syncthreads();
    if (wid == 0) {
        float v = (lane < 8) ? red[lane] : 0.f;
        for (int o = 4; o; o >>= 1) v += __shfl_down_sync(0xffffffffu, v, o);
        if (lane == 0) g_lpart[blockIdx.x] = v;
    }
}

__global__ void k_loss2(float* __restrict__ out) {
    int lane = threadIdx.x;   // 64 threads
    float v = g_lpart[lane];
    for (int o = 16; o; o >>= 1) v += __shfl_down_sync(0xffffffffu, v, o);
    __shared__ float red[2];
    if ((lane & 31) == 0) red[lane >> 5] = v;
    __syncthreads();
    if (lane == 0) out[0] = (red[0] + red[1]) / (float)(NBATCH*NPIX);
}

extern "C" void kernel_launch(void* const* d_in, const int* in_sizes, int n_in,
                              void* d_out, int out_size) {
    const float* images  = (const float*)d_in[0];
    const float* predict = (const float*)d_in[1];
    if (n_in >= 2 && in_sizes[0] < in_sizes[1]) {
        const float* tmp = images; images = predict; predict = tmp;
    }

    k_rsg<<<(NPIX + 255)/256, 256>>>();
    k_resize<<<(NBATCH*NPIX + 127)/128, 128>>>(images);
    k_probs<<<(NBATCH*NPIX + 127)/128, 128>>>(predict);
    k_sums<<<dim3(NPIX, NBATCH), 256>>>();
    k_keff<<<dim3((KSTRIDE_H/2 + 255)/256, NPIX, NBATCH), 256>>>();
    for (int it = 0; it < NITERS; it++) {
        int dir = it & 1;
        k_msg<<<dim3((NPIX + TILE_M - 1)/TILE_M, KSPLIT, NBATCH), 128>>>(dir);
        k_update<<<(NBATCH*NPIX + 127)/128, 128>>>(dir);
    }
    k_loss1<<<NLB, 256>>>();
    k_loss2<<<1, 64>>>((float*)d_out);
}